// round 11
// baseline (speedup 1.0000x reference)
#include <cuda_runtime.h>
#include <cstdint>

#define N_TOKENS 8192
#define IN_CH    4096
#define OUT_CH   4096
#define RANK     16
#define TOK      16                    // tokens per block
#define KH       2048                  // k half staged (R: 16 x 2048 = 128 KB)
#define OCH      2048                  // o chunk staged  (Lt: 16 x 2048 = 128 KB)
#define DSMEM    (RANK * KH * 4)       // 128 KB

typedef unsigned long long u64;

__device__ __forceinline__ u64 f2fma(u64 a, u64 b, u64 c) {
    u64 d;
    asm("fma.rn.f32x2 %0, %1, %2, %3;" : "=l"(d) : "l"(a), "l"(b), "l"(c));
    return d;
}
__device__ __forceinline__ u64 splat2(float v) {
    u64 d;
    asm("mov.b64 %0, {%1, %1};" : "=l"(d) : "f"(v));
    return d;
}

// ----------------------------------------------------------------------------
// Fused: out = x @ (L@R)^T + bias, rank-16 low-rank path, ONE kernel.
// Block: 16 tokens, 512 thr, 128 KB dynamic smem reused:
//   Phase A: stage R k-half (16x2048), warp = (tokquad, rankhalf, ksub):
//            4 tok x 8 ranks x 1024 k; acc in f32x2; partials -> smem.
//   Phase B: stage Lt o-chunk transposed (16x2048); thread = 4 outputs x
//            ALL 16 tokens (acc 32 u64) -> bcast-LDS per FFMA2 = 0.56.
// x read once (streaming), out written once; read & write interleave.
// ----------------------------------------------------------------------------
__global__ void __launch_bounds__(512)
fused(const float* __restrict__ x, const float* __restrict__ Rm,
      const float* __restrict__ Lm, const float* __restrict__ bias,
      float* __restrict__ out) {
    extern __shared__ __align__(16) float sbuf[];      // 128 KB: Rs then Lt
    __shared__ __align__(16) float ts_part[2][TOK][RANK];   // 2 KB
    __shared__ __align__(16) u64   ts2[TOK][RANK];          // 2 KB

    const int tid  = threadIdx.x;
    const int warp = tid >> 5;
    const int lane = tid & 31;
    const int tokbase = blockIdx.x * TOK;

    // ---------------- Phase A: t = x @ R^T ----------------
    const int q     = warp >> 2;          // token quad 0..3
    const int rh    = (warp >> 1) & 1;    // rank half
    const int s     = warp & 1;           // k sub-half
    const int tok0  = q * 4;
    const int rbase = rh * 8;
    const int kbase = s * 1024;

    u64 acc[4][8];
#pragma unroll
    for (int t = 0; t < 4; t++)
#pragma unroll
        for (int r = 0; r < 8; r++) acc[t][r] = 0ull;

    const float* xg = x + (size_t)tokbase * IN_CH;

#pragma unroll 1
    for (int h = 0; h < 2; h++) {
        if (h > 0) __syncthreads();               // done reading previous Rs
        // stage R[0:16][h*KH : (h+1)*KH]: 8192 float4, 16 per thread
#pragma unroll
        for (int j = 0; j < 16; j++) {
            const int linear = tid + 512 * j;
            const int row    = linear >> 9;        // KH/4 = 512 float4 per row
            const int colf   = (linear & 511) << 2;
            *reinterpret_cast<float4*>(&sbuf[row * KH + colf]) =
                *reinterpret_cast<const float4*>(&Rm[(size_t)row * IN_CH + h * KH + colf]);
        }
        __syncthreads();

        const float* xh = xg + h * KH + kbase + lane * 4;
        const float* Rw = sbuf + (size_t)rbase * KH + kbase + lane * 4;
#pragma unroll 2
        for (int i = 0; i < 8; i++) {
            const int kk = i * 128;
            const uint4 xv0 = __ldcs(reinterpret_cast<const uint4*>(xh + (size_t)(tok0 + 0) * IN_CH + kk));
            const uint4 xv1 = __ldcs(reinterpret_cast<const uint4*>(xh + (size_t)(tok0 + 1) * IN_CH + kk));
            const uint4 xv2 = __ldcs(reinterpret_cast<const uint4*>(xh + (size_t)(tok0 + 2) * IN_CH + kk));
            const uint4 xv3 = __ldcs(reinterpret_cast<const uint4*>(xh + (size_t)(tok0 + 3) * IN_CH + kk));
            const ulonglong2 x0 = *reinterpret_cast<const ulonglong2*>(&xv0);
            const ulonglong2 x1 = *reinterpret_cast<const ulonglong2*>(&xv1);
            const ulonglong2 x2 = *reinterpret_cast<const ulonglong2*>(&xv2);
            const ulonglong2 x3 = *reinterpret_cast<const ulonglong2*>(&xv3);
#pragma unroll
            for (int r = 0; r < 8; r++) {
                const ulonglong2 rv =
                    *reinterpret_cast<const ulonglong2*>(Rw + (size_t)r * KH + kk);
                acc[0][r] = f2fma(x0.x, rv.x, acc[0][r]);
                acc[0][r] = f2fma(x0.y, rv.y, acc[0][r]);
                acc[1][r] = f2fma(x1.x, rv.x, acc[1][r]);
                acc[1][r] = f2fma(x1.y, rv.y, acc[1][r]);
                acc[2][r] = f2fma(x2.x, rv.x, acc[2][r]);
                acc[2][r] = f2fma(x2.y, rv.y, acc[2][r]);
                acc[3][r] = f2fma(x3.x, rv.x, acc[3][r]);
                acc[3][r] = f2fma(x3.y, rv.y, acc[3][r]);
            }
        }
    }

    // lane-reduce; lane 0 writes this warp's partial (8 ranks x 4 tokens)
#pragma unroll
    for (int t = 0; t < 4; t++) {
        float sv[8];
#pragma unroll
        for (int r = 0; r < 8; r++) {
            float2 v = *reinterpret_cast<float2*>(&acc[t][r]);
            sv[r] = v.x + v.y;
        }
#pragma unroll
        for (int off = 16; off > 0; off >>= 1) {
#pragma unroll
            for (int r = 0; r < 8; r++)
                sv[r] += __shfl_xor_sync(0xffffffffu, sv[r], off);
        }
        if (lane == 0) {
            float4* o = reinterpret_cast<float4*>(&ts_part[s][tok0 + t][rbase]);
            o[0] = make_float4(sv[0], sv[1], sv[2], sv[3]);
            o[1] = make_float4(sv[4], sv[5], sv[6], sv[7]);
        }
    }
    __syncthreads();   // partials visible; Rs buffer free

    // combine k-sub partials, splat to f32x2
    if (tid < TOK * RANK) {
        const int tok = tid >> 4;
        const int r   = tid & 15;
        ts2[tok][r] = splat2(ts_part[0][tok][r] + ts_part[1][tok][r]);
    }

    // ---------------- Phase B: out = t @ L^T + bias ----------------
#pragma unroll 1
    for (int c = 0; c < 2; c++) {
        if (c > 0) __syncthreads();               // done reading previous Lt
        // stage Lt[r][ol] for o in [c*OCH, (c+1)*OCH): 2048 rows x 16 floats
#pragma unroll
        for (int j = 0; j < 4; j++) {
            const int ol = tid + 512 * j;
            const float4* lr = reinterpret_cast<const float4*>(
                Lm + (size_t)(c * OCH + ol) * RANK);
            float4 a = lr[0], b = lr[1], d2 = lr[2], e = lr[3];
            sbuf[0 * OCH + ol]  = a.x;  sbuf[1 * OCH + ol]  = a.y;
            sbuf[2 * OCH + ol]  = a.z;  sbuf[3 * OCH + ol]  = a.w;
            sbuf[4 * OCH + ol]  = b.x;  sbuf[5 * OCH + ol]  = b.y;
            sbuf[6 * OCH + ol]  = b.z;  sbuf[7 * OCH + ol]  = b.w;
            sbuf[8 * OCH + ol]  = d2.x; sbuf[9 * OCH + ol]  = d2.y;
            sbuf[10 * OCH + ol] = d2.z; sbuf[11 * OCH + ol] = d2.w;
            sbuf[12 * OCH + ol] = e.x;  sbuf[13 * OCH + ol] = e.y;
            sbuf[14 * OCH + ol] = e.z;  sbuf[15 * OCH + ol] = e.w;
        }
        __syncthreads();   // Lt ready (and ts2 ready when c==0)

        const int ol4 = tid * 4;                   // local o, 4 per thread
        const int og  = c * OCH + ol4;             // global o
        const ulonglong2 bv = *reinterpret_cast<const ulonglong2*>(&bias[og]);

        u64 oacc[TOK][2];
#pragma unroll
        for (int t = 0; t < TOK; t++) { oacc[t][0] = bv.x; oacc[t][1] = bv.y; }

#pragma unroll
        for (int r = 0; r < RANK; r++) {
            const ulonglong2 Lv =
                *reinterpret_cast<const ulonglong2*>(&sbuf[r * OCH + ol4]);
#pragma unroll
            for (int t = 0; t < TOK; t++) {
                const u64 t2 = ts2[t][r];          // broadcast LDS.64
                oacc[t][0] = f2fma(t2, Lv.x, oacc[t][0]);
                oacc[t][1] = f2fma(t2, Lv.y, oacc[t][1]);
            }
        }

        float* op = out + (size_t)tokbase * OUT_CH + og;
#pragma unroll
        for (int t = 0; t < TOK; t++) {
            ulonglong2 o;
            o.x = oacc[t][0];
            o.y = oacc[t][1];
            *reinterpret_cast<ulonglong2*>(op + (size_t)t * OUT_CH) = o;
        }
    }
}

extern "C" void kernel_launch(void* const* d_in, const int* in_sizes, int n_in,
                              void* d_out, int out_size) {
    (void)in_sizes; (void)n_in; (void)out_size;
    const float* x    = (const float*)d_in[0];   // [8192, 4096]
    const float* Lm   = (const float*)d_in[1];   // [4096, 16]
    const float* Rm   = (const float*)d_in[2];   // [16, 4096]
    const float* bias = (const float*)d_in[3];   // [4096]
    float* out = (float*)d_out;                  // [8192, 4096]

    cudaFuncSetAttribute(fused, cudaFuncAttributeMaxDynamicSharedMemorySize, DSMEM);
    fused<<<N_TOKENS / TOK, 512, DSMEM>>>(x, Rm, Lm, bias, out);
}